// round 8
// baseline (speedup 1.0000x reference)
#include <cuda_runtime.h>
#include <cuda_bf16.h>
#include <mma.h>
#include <cstdint>

using namespace nvcuda;

#define T_    128
#define B_    256
#define D_    1024
#define H_    1024
#define V_    32000
#define TAGS_ 1024
#define GQ    32      // 4 gates * 8 qubits

// ---------------- scratch (static device globals; no cudaMalloc allowed) ----
__device__ float          g_embproj[V_ * GQ];           // emb @ Wg_x
__device__ __nv_bfloat16  g_lstm[(size_t)T_ * B_ * H_]; // lstm_out bf16
__device__ __nv_bfloat16  g_wtag[H_ * TAGS_];           // W_tag bf16

// ---------------- helpers ----------------------------------------------------
__device__ __forceinline__ void cp16(void* smem, const void* gmem) {
    unsigned sa = (unsigned)__cvta_generic_to_shared(smem);
    asm volatile("cp.async.cg.shared.global [%0], [%1], 16;\n" :: "r"(sa), "l"(gmem));
}
__device__ __forceinline__ float fast_sigmoid(float x) {
    return 0.5f + 0.5f * __tanhf(0.5f * x);
}
// packed f32x2 (Blackwell base ISA; FFMA2 in SASS)
__device__ __forceinline__ uint64_t fma2(uint64_t a, uint64_t b, uint64_t c) {
    uint64_t d;
    asm("fma.rn.f32x2 %0, %1, %2, %3;" : "=l"(d) : "l"(a), "l"(b), "l"(c));
    return d;
}
__device__ __forceinline__ uint64_t pk2(uint32_t lo, uint32_t hi) {
    uint64_t d;
    asm("mov.b64 %0, {%1, %2};" : "=l"(d) : "r"(lo), "r"(hi));
    return d;
}
__device__ __forceinline__ float f2lo(uint64_t v) { return __uint_as_float((uint32_t)v); }
__device__ __forceinline__ float f2hi(uint64_t v) { return __uint_as_float((uint32_t)(v >> 32)); }

// ---------------- K0: W_tag -> bf16 -----------------------------------------
__global__ void wtag_convert(const float* __restrict__ w) {
    int i = blockIdx.x * 256 + threadIdx.x;
    g_wtag[i] = __float2bfloat16(w[i]);
}

// ---------------- K1: embproj = emb @ Wg[:, :D, :]  (32000 x 32) ------------
__global__ __launch_bounds__(256) void embproj_kernel(const float* __restrict__ emb,
                                                      const float* __restrict__ Wg) {
    __shared__ float As[128][33];
    __shared__ __align__(16) float Bs[32][36];
    int tid = threadIdx.x;
    int v0  = blockIdx.x * 128;
    int tr  = tid >> 3, tc = tid & 7;
    uint64_t accp[4][2] = {};

    for (int k0 = 0; k0 < D_; k0 += 32) {
        #pragma unroll
        for (int i = 0; i < 4; i++) {
            int f4  = tid + i * 256;
            int row = f4 >> 3, c4 = (f4 & 7) * 4;
            float4 a = *(const float4*)&emb[(size_t)(v0 + row) * D_ + k0 + c4];
            As[row][c4] = a.x; As[row][c4 + 1] = a.y;
            As[row][c4 + 2] = a.z; As[row][c4 + 3] = a.w;
        }
        #pragma unroll
        for (int i = 0; i < 4; i++) {
            int idx = tid + i * 256;
            int k = idx >> 5, gq = idx & 31;
            Bs[k][gq] = Wg[(gq >> 3) * (2048 * 8) + (k0 + k) * 8 + (gq & 7)];
        }
        __syncthreads();
        #pragma unroll
        for (int k = 0; k < 32; k++) {
            ulonglong2 b2 = *(const ulonglong2*)&Bs[k][tc * 4];
            #pragma unroll
            for (int i = 0; i < 4; i++) {
                uint32_t ar = __float_as_uint(As[tr * 4 + i][k]);
                uint64_t aa = pk2(ar, ar);
                accp[i][0] = fma2(aa, b2.x, accp[i][0]);
                accp[i][1] = fma2(aa, b2.y, accp[i][1]);
            }
        }
        __syncthreads();
    }
    #pragma unroll
    for (int i = 0; i < 4; i++) {
        float4 o = make_float4(f2lo(accp[i][0]), f2hi(accp[i][0]),
                               f2lo(accp[i][1]), f2hi(accp[i][1]));
        *(float4*)&g_embproj[(v0 + tr * 4 + i) * GQ + tc * 4] = o;
    }
}

// ---------------- K2: LSTM, bf16-paired weights + f32x2 matvec ---------------
// 512 thr/CTA, 2 hidden units/thread, 2 batch/CTA, 128 CTAs (1 wave).
// smem: Wkp[32][512] u32 (bf16x2 k-pairs) | h0s[1024] | h1s[1024]
//       | xq0/1[4096] | qc0/1[32]
#define LSTM_SMEM ((16384 + 2 * 1024 + 2 * 4096 + 64) * 4)

__device__ __forceinline__ void gate_update(const float4* qc, const float* wp,
                                            const float* bpv, float& c, float& h) {
    float pj[4];
    #pragma unroll
    for (int g = 0; g < 4; g++) {
        float4 a = qc[2 * g], b = qc[2 * g + 1];
        float s = bpv[g];
        s = fmaf(a.x, wp[g * 8 + 0], s); s = fmaf(a.y, wp[g * 8 + 1], s);
        s = fmaf(a.z, wp[g * 8 + 2], s); s = fmaf(a.w, wp[g * 8 + 3], s);
        s = fmaf(b.x, wp[g * 8 + 4], s); s = fmaf(b.y, wp[g * 8 + 5], s);
        s = fmaf(b.z, wp[g * 8 + 6], s); s = fmaf(b.w, wp[g * 8 + 7], s);
        pj[g] = s;
    }
    float fg = fast_sigmoid(pj[0]);
    float ig = fast_sigmoid(pj[1]);
    float gg = __tanhf(pj[2]);
    float og = fast_sigmoid(pj[3]);
    c = fg * c + ig * gg;
    h = og * __tanhf(c);
}

__global__ __launch_bounds__(512, 1) void lstm_kernel(
    const int*   __restrict__ sentence,
    const float* __restrict__ Wg,
    const float* __restrict__ bg,
    const float* __restrict__ theta,
    const float* __restrict__ Wp,
    const float* __restrict__ bp) {
    extern __shared__ float sm[];
    uint32_t* Wkp = (uint32_t*)sm;         // [32 gq][512 k-pairs] bf16x2
    float* h0s = sm + 16384;               // 1024
    float* h1s = h0s + 1024;               // 1024
    float* xq0 = h1s + 1024;               // 4096
    float* xq1 = xq0 + 4096;               // 4096
    float* qc0 = xq1 + 4096;               // 32 (16B aligned)
    float* qc1 = qc0 + 32;                 // 32

    const int tid  = threadIdx.x;
    const int warp = tid >> 5, lane = tid & 31;
    const int b0   = blockIdx.x * 2;

    // Wkp[gq][kp] = bf16x2(Wg[g][D+2kp][q], Wg[g][D+2kp+1][q])
    #pragma unroll 4
    for (int it = 0; it < 32; it++) {
        int p  = tid + it * 512;            // 16384 total
        int gq = p >> 9, kp = p & 511;
        int g  = gq >> 3, q = gq & 7;
        const float* src = Wg + g * (2048 * 8) + (size_t)(1024 + 2 * kp) * 8 + q;
        uint32_t l16 = (uint32_t)__bfloat16_as_ushort(__float2bfloat16(src[0]));
        uint32_t h16 = (uint32_t)__bfloat16_as_ushort(__float2bfloat16(src[8]));
        Wkp[gq * 512 + kp] = l16 | (h16 << 16);
    }
    // xq[b][t][gq] = embproj[token][gq] + bg[gq] + theta[gq]
    #pragma unroll
    for (int it = 0; it < 16; it++) {
        int p  = tid + it * 512;
        int bb = p >> 12, r = p & 4095;
        int t  = r >> 5, gq = r & 31;
        int token = sentence[t * B_ + b0 + bb];
        (bb ? xq1 : xq0)[t * 32 + gq] =
            g_embproj[token * GQ + gq] + bg[gq] + theta[gq];
    }
    // per-thread Wp slices for j = tid and j = tid + 512
    float wpreg[64], bpv[8];
    #pragma unroll
    for (int k = 0; k < 32; k++) {
        wpreg[k]      = Wp[k * H_ + tid];
        wpreg[32 + k] = Wp[k * H_ + tid + 512];
    }
    #pragma unroll
    for (int g = 0; g < 4; g++) {
        bpv[g]     = bp[g * H_ + tid];
        bpv[4 + g] = bp[g * H_ + tid + 512];
    }

    h0s[tid] = 0.f; h0s[tid + 512] = 0.f;
    h1s[tid] = 0.f; h1s[tid + 512] = 0.f;
    float h0a = 0.f, h0b = 0.f, h1a = 0.f, h1b = 0.f;
    float c0a = 0.f, c0b = 0.f, c1a = 0.f, c1b = 0.f;
    __syncthreads();

    const int gq0 = warp, gq1 = warp + 16;
    const uint4* w0r = (const uint4*)(Wkp + gq0 * 512);   // 128 uint4/row
    const uint4* w1r = (const uint4*)(Wkp + gq1 * 512);
    const ulonglong2* h0p = (const ulonglong2*)h0s;       // float pairs
    const ulonglong2* h1p = (const ulonglong2*)h1s;

    for (int t = 0; t < T_; t++) {
        // matvec: lanes parallel over k (8 bf16 weights per uint4);
        // packed f32x2 over k-pairs; warp owns (gq0, gq1) x (b0, b1).
        uint64_t A00 = 0, A01 = 0, A10 = 0, A11 = 0;
        #pragma unroll
        for (int i = 0; i < 4; i++) {
            int idx = lane + 32 * i;        // uint4 index (8 k)
            uint4 wa = w0r[idx];
            uint4 wb = w1r[idx];
            ulonglong2 hA = h0p[2 * idx], hB = h0p[2 * idx + 1];
            ulonglong2 gA = h1p[2 * idx], gB = h1p[2 * idx + 1];
            uint32_t wv;
            uint64_t wp;
            wv = wa.x; wp = pk2(wv << 16, wv & 0xffff0000u);
            A00 = fma2(hA.x, wp, A00); A10 = fma2(gA.x, wp, A10);
            wv = wa.y; wp = pk2(wv << 16, wv & 0xffff0000u);
            A00 = fma2(hA.y, wp, A00); A10 = fma2(gA.y, wp, A10);
            wv = wa.z; wp = pk2(wv << 16, wv & 0xffff0000u);
            A00 = fma2(hB.x, wp, A00); A10 = fma2(gB.x, wp, A10);
            wv = wa.w; wp = pk2(wv << 16, wv & 0xffff0000u);
            A00 = fma2(hB.y, wp, A00); A10 = fma2(gB.y, wp, A10);
            wv = wb.x; wp = pk2(wv << 16, wv & 0xffff0000u);
            A01 = fma2(hA.x, wp, A01); A11 = fma2(gA.x, wp, A11);
            wv = wb.y; wp = pk2(wv << 16, wv & 0xffff0000u);
            A01 = fma2(hA.y, wp, A01); A11 = fma2(gA.y, wp, A11);
            wv = wb.z; wp = pk2(wv << 16, wv & 0xffff0000u);
            A01 = fma2(hB.x, wp, A01); A11 = fma2(gB.x, wp, A11);
            wv = wb.w; wp = pk2(wv << 16, wv & 0xffff0000u);
            A01 = fma2(hB.y, wp, A01); A11 = fma2(gB.y, wp, A11);
        }
        float a00 = f2lo(A00) + f2hi(A00);
        float a01 = f2lo(A01) + f2hi(A01);
        float a10 = f2lo(A10) + f2hi(A10);
        float a11 = f2lo(A11) + f2hi(A11);
        #pragma unroll
        for (int off = 16; off > 0; off >>= 1) {
            a00 += __shfl_xor_sync(~0u, a00, off);
            a01 += __shfl_xor_sync(~0u, a01, off);
            a10 += __shfl_xor_sync(~0u, a10, off);
            a11 += __shfl_xor_sync(~0u, a11, off);
        }
        if (lane == 0) {
            qc0[gq0] = __cosf(a00 + xq0[t * 32 + gq0]);
            qc0[gq1] = __cosf(a01 + xq0[t * 32 + gq1]);
            qc1[gq0] = __cosf(a10 + xq1[t * 32 + gq0]);
            qc1[gq1] = __cosf(a11 + xq1[t * 32 + gq1]);
        }
        __syncthreads();

        const float4* q0 = (const float4*)qc0;
        const float4* q1 = (const float4*)qc1;
        gate_update(q0, wpreg,      bpv,     c0a, h0a);
        gate_update(q0, wpreg + 32, bpv + 4, c0b, h0b);
        gate_update(q1, wpreg,      bpv,     c1a, h1a);
        gate_update(q1, wpreg + 32, bpv + 4, c1b, h1b);

        size_t base = ((size_t)t * B_ + b0) * H_;
        g_lstm[base + tid]            = __float2bfloat16(h0a);
        g_lstm[base + tid + 512]      = __float2bfloat16(h0b);
        g_lstm[base + H_ + tid]       = __float2bfloat16(h1a);
        g_lstm[base + H_ + tid + 512] = __float2bfloat16(h1b);
        h0s[tid] = h0a; h0s[tid + 512] = h0b;
        h1s[tid] = h1a; h1s[tid + 512] = h1b;
        __syncthreads();
    }
}

// ---------------- K3: fused tag GEMM (bf16 WMMA, 3-stage, 1 sync/iter) ------
// block = one (t, 128-tag chunk): tile 256(b) x 128(tags), K = 1024, KT = 64.
// b_tag cancels in batch-axis log_softmax.
#define A_STG (256 * 72)     // halves per A stage (ld = 72)
#define B_STG (64 * 136)     // halves per B stage (ld = 136)
#define TAG_SMEM (3 * (A_STG + B_STG) * 2)   // 162816 B; epilogue aliases

__global__ __launch_bounds__(256, 1) void tag_kernel(float* __restrict__ out) {
    extern __shared__ char smraw[];
    __nv_bfloat16* Asm = (__nv_bfloat16*)smraw;        // 3 stages 256x72
    __nv_bfloat16* Bsm = Asm + 3 * A_STG;              // 3 stages 64x136
    float* Osm = (float*)smraw;                        // 256 x 136 fp32 (alias)
    float* red = Osm + 256 * 136;

    const int tid = threadIdx.x;
    const int t   = blockIdx.y;
    const int c0  = blockIdx.x * 128;
    const int w   = tid >> 5;
    const int wy  = w >> 1;        // 0..3 -> 64-row block
    const int wx  = w & 1;         // 0..1 -> 64-col block

    wmma::fragment<wmma::accumulator, 16, 16, 16, float> acc[4][4];
    #pragma unroll
    for (int i = 0; i < 4; i++)
        #pragma unroll
        for (int j = 0; j < 4; j++) wmma::fill_fragment(acc[i][j], 0.f);

    auto issue_tile = [&](int kt) {
        int s  = kt % 3;
        int k0 = kt * 64;
        __nv_bfloat16* As = Asm + s * A_STG;
        __nv_bfloat16* Bs = Bsm + s * B_STG;
        #pragma unroll
        for (int i = 0; i < 8; i++) {             // A: 256x64 = 2048 cp16
            int e = tid + i * 256;
            int row = e >> 3, c8 = (e & 7) * 8;
            cp16(&As[row * 72 + c8],
                 &g_lstm[((size_t)t * B_ + row) * H_ + k0 + c8]);
        }
        #pragma unroll
        for (int i = 0; i < 4; i++) {             // B: 64x128 = 1024 cp16
            int e = tid + i * 256;
            int row = e >> 4, c8 = (e & 15) * 8;
            cp16(&Bs[row * 136 + c8],
                 &g_wtag[(size_t)(k0 + row) * TAGS_ + c0 + c8]);
        }
        asm volatile("cp.async.commit_group;\n" ::);
    };

    issue_tile(0);
    issue_tile(1);
    for (int kt = 0; kt < 16; kt++) {
        if (kt < 15) asm volatile("cp.async.wait_group 1;\n" ::);
        else         asm volatile("cp.async.wait_group 0;\n" ::);
        __syncthreads();   // stage kt ready for ALL warps; also proves compute
                           // kt-1 finished everywhere (safe to overwrite kt+2%3)
        int s = kt % 3;
        const __nv_bfloat16* As = Asm + s * A_STG;
        const __nv_bfloat16* Bs = Bsm + s * B_STG;
        #pragma unroll
        for (int ks = 0; ks < 64; ks += 16) {
            wmma::fragment<wmma::matrix_a, 16, 16, 16, __nv_bfloat16, wmma::row_major> af[4];
            wmma::fragment<wmma::matrix_b, 16, 16, 16, __nv_bfloat16, wmma::row_major> bf[4];
            #pragma unroll
            for (int i = 0; i < 4; i++)
                wmma::load_matrix_sync(af[i], &As[(wy * 64 + i * 16) * 72 + ks], 72);
            #pragma unroll
            for (int j = 0; j < 4; j++)
                wmma::load_matrix_sync(bf[j], &Bs[ks * 136 + wx * 64 + j * 16], 136);
            #pragma unroll
            for (int i = 0; i < 4; i++)
                #pragma unroll
                for (int j = 0; j < 4; j++)
                    wmma::mma_sync(acc[i][j], af[i], bf[j], acc[i][j]);
        }
        if (kt + 2 < 16) issue_tile(kt + 2);
    }
    __syncthreads();   // all compute done before Osm aliases stage buffers

    #pragma unroll
    for (int i = 0; i < 4; i++)
        #pragma unroll
        for (int j = 0; j < 4; j++)
            wmma::store_matrix_sync(&Osm[(wy * 64 + i * 16) * 136 + wx * 64 + j * 16],
                                    acc[i][j], 136, wmma::mem_row_major);
    __syncthreads();

    // log_softmax over the 256 rows (batch) per column (tag); 256 threads
    const int p = tid >> 7;        // 0..1, 128 rows each
    const int c = tid & 127;
    float m = -1e30f;
    #pragma unroll 8
    for (int i = 0; i < 128; i++) m = fmaxf(m, Osm[(p * 128 + i) * 136 + c]);
    red[p * 128 + c] = m;
    __syncthreads();
    float M = fmaxf(red[c], red[128 + c]);
    float ssum = 0.f;
    #pragma unroll 8
    for (int i = 0; i < 128; i++) ssum += __expf(Osm[(p * 128 + i) * 136 + c] - M);
    __syncthreads();
    red[p * 128 + c] = ssum;
    __syncthreads();
    float lse = M + logf(red[c] + red[128 + c]);
    #pragma unroll 8
    for (int i = 0; i < 128; i++) {
        int b = p * 128 + i;
        out[((size_t)t * B_ + b) * TAGS_ + c0 + c] = Osm[b * 136 + c] - lse;
    }
}

// ---------------- launch -----------------------------------------------------
extern "C" void kernel_launch(void* const* d_in, const int* in_sizes, int n_in,
                              void* d_out, int out_size) {
    const int*   sentence = (const int*)  d_in[0];
    const float* emb      = (const float*)d_in[1];
    const float* Wg       = (const float*)d_in[2];
    const float* bg       = (const float*)d_in[3];
    const float* theta    = (const float*)d_in[4];
    const float* Wp       = (const float*)d_in[5];
    const float* bp       = (const float*)d_in[6];
    const float* W_tag    = (const float*)d_in[7];
    // d_in[8] = b_tag: cancels in log_softmax over batch axis -> unused
    float* out = (float*)d_out;

    cudaFuncSetAttribute(lstm_kernel, cudaFuncAttributeMaxDynamicSharedMemorySize, LSTM_SMEM);
    cudaFuncSetAttribute(tag_kernel,  cudaFuncAttributeMaxDynamicSharedMemorySize, TAG_SMEM);

    wtag_convert<<<(H_ * TAGS_) / 256, 256>>>(W_tag);
    embproj_kernel<<<V_ / 128, 256>>>(emb, Wg);
    lstm_kernel<<<B_ / 2, 512, LSTM_SMEM>>>(sentence, Wg, bg, theta, Wp, bp);
    dim3 g3(TAGS_ / 128, T_);
    tag_kernel<<<g3, 256, TAG_SMEM>>>(out);
}

// round 9
// speedup vs baseline: 1.1594x; 1.1594x over previous
#include <cuda_runtime.h>
#include <cuda_bf16.h>
#include <mma.h>
#include <cstdint>

using namespace nvcuda;

#define T_    128
#define B_    256
#define D_    1024
#define H_    1024
#define V_    32000
#define TAGS_ 1024
#define GQ    32      // 4 gates * 8 qubits

// ---------------- scratch (static device globals; no cudaMalloc allowed) ----
__device__ float          g_embproj[V_ * GQ];           // emb @ Wg_x
__device__ __nv_bfloat16  g_lstm[(size_t)T_ * B_ * H_]; // lstm_out bf16
__device__ __nv_bfloat16  g_wtag[H_ * TAGS_];           // W_tag bf16

// ---------------- helpers ----------------------------------------------------
__device__ __forceinline__ void cp16(void* smem, const void* gmem) {
    unsigned sa = (unsigned)__cvta_generic_to_shared(smem);
    asm volatile("cp.async.cg.shared.global [%0], [%1], 16;\n" :: "r"(sa), "l"(gmem));
}
__device__ __forceinline__ float fast_sigmoid(float x) {
    return 0.5f + 0.5f * __tanhf(0.5f * x);
}
__device__ __forceinline__ float bflo(uint32_t v) { return __uint_as_float(v << 16); }
__device__ __forceinline__ float bfhi(uint32_t v) { return __uint_as_float(v & 0xffff0000u); }

// ---------------- K0: W_tag -> bf16 -----------------------------------------
__global__ void wtag_convert(const float* __restrict__ w) {
    int i = blockIdx.x * 256 + threadIdx.x;
    g_wtag[i] = __float2bfloat16(w[i]);
}

// ---------------- K1: embproj = emb @ Wg[:, :D, :]  (32000 x 32) ------------
__global__ __launch_bounds__(256) void embproj_kernel(const float* __restrict__ emb,
                                                      const float* __restrict__ Wg) {
    __shared__ float As[128][33];
    __shared__ __align__(16) float Bs[32][36];
    int tid = threadIdx.x;
    int v0  = blockIdx.x * 128;
    int tr  = tid >> 3, tc = tid & 7;
    float acc[4][4] = {};

    for (int k0 = 0; k0 < D_; k0 += 32) {
        #pragma unroll
        for (int i = 0; i < 4; i++) {
            int f4  = tid + i * 256;
            int row = f4 >> 3, c4 = (f4 & 7) * 4;
            float4 a = *(const float4*)&emb[(size_t)(v0 + row) * D_ + k0 + c4];
            As[row][c4] = a.x; As[row][c4 + 1] = a.y;
            As[row][c4 + 2] = a.z; As[row][c4 + 3] = a.w;
        }
        #pragma unroll
        for (int i = 0; i < 4; i++) {
            int idx = tid + i * 256;
            int k = idx >> 5, gq = idx & 31;
            Bs[k][gq] = Wg[(gq >> 3) * (2048 * 8) + (k0 + k) * 8 + (gq & 7)];
        }
        __syncthreads();
        #pragma unroll
        for (int k = 0; k < 32; k++) {
            float4 b4 = *(const float4*)&Bs[k][tc * 4];
            #pragma unroll
            for (int i = 0; i < 4; i++) {
                float a = As[tr * 4 + i][k];
                acc[i][0] += a * b4.x; acc[i][1] += a * b4.y;
                acc[i][2] += a * b4.z; acc[i][3] += a * b4.w;
            }
        }
        __syncthreads();
    }
    #pragma unroll
    for (int i = 0; i < 4; i++) {
        float4 o = make_float4(acc[i][0], acc[i][1], acc[i][2], acc[i][3]);
        *(float4*)&g_embproj[(v0 + tr * 4 + i) * GQ + tc * 4] = o;
    }
}

// ---------------- K2: LSTM, k-split matvec (lane = gq, warp = k-slice) -------
// 512 thr/CTA, 2 hidden units/thread, 2 batch/CTA, 128 CTAs (1 wave).
// smem: Wkp[512 kpairs][32 gq] bf16x2 (64KB) | h0s/h1s[1024] | xq0/1[4096]
//       | qc0/1[32] | red0/1[16*33]
#define LSTM_SMEM ((16384 + 2 * 1024 + 2 * 4096 + 64 + 2 * 16 * 33) * 4)

__device__ __forceinline__ void gate_update(const float4* qc, const float* wp,
                                            const float* bpv, float& c, float& h) {
    float pj[4];
    #pragma unroll
    for (int g = 0; g < 4; g++) {
        float4 a = qc[2 * g], b = qc[2 * g + 1];
        float s = bpv[g];
        s = fmaf(a.x, wp[g * 8 + 0], s); s = fmaf(a.y, wp[g * 8 + 1], s);
        s = fmaf(a.z, wp[g * 8 + 2], s); s = fmaf(a.w, wp[g * 8 + 3], s);
        s = fmaf(b.x, wp[g * 8 + 4], s); s = fmaf(b.y, wp[g * 8 + 5], s);
        s = fmaf(b.z, wp[g * 8 + 6], s); s = fmaf(b.w, wp[g * 8 + 7], s);
        pj[g] = s;
    }
    float fg = fast_sigmoid(pj[0]);
    float ig = fast_sigmoid(pj[1]);
    float gg = __tanhf(pj[2]);
    float og = fast_sigmoid(pj[3]);
    c = fg * c + ig * gg;
    h = og * __tanhf(c);
}

__global__ __launch_bounds__(512, 1) void lstm_kernel(
    const int*   __restrict__ sentence,
    const float* __restrict__ Wg,
    const float* __restrict__ bg,
    const float* __restrict__ theta,
    const float* __restrict__ Wp,
    const float* __restrict__ bp) {
    extern __shared__ float sm[];
    uint32_t* Wkp = (uint32_t*)sm;         // [512 kp][32 gq] bf16x2
    float* h0s  = sm + 16384;              // 1024
    float* h1s  = h0s + 1024;              // 1024
    float* xq0  = h1s + 1024;              // 4096
    float* xq1  = xq0 + 4096;              // 4096
    float* qc0  = xq1 + 4096;              // 32 (16B aligned)
    float* qc1  = qc0 + 32;                // 32
    float* red0 = qc1 + 32;                // 16 x 33
    float* red1 = red0 + 16 * 33;          // 16 x 33

    const int tid  = threadIdx.x;
    const int warp = tid >> 5, lane = tid & 31;
    const int b0   = blockIdx.x * 2;

    // Wkp[kp][gq] = bf16x2(Wg[g][D+2kp][q], Wg[g][D+2kp+1][q]),  gq = g*8+q
    #pragma unroll 4
    for (int it = 0; it < 32; it++) {
        int p  = tid + it * 512;            // 16384 total
        int kp = p >> 5, gq = p & 31;
        int g  = gq >> 3, q = gq & 7;
        const float* src = Wg + g * (2048 * 8) + (size_t)(1024 + 2 * kp) * 8 + q;
        uint32_t l16 = (uint32_t)__bfloat16_as_ushort(__float2bfloat16(src[0]));
        uint32_t h16 = (uint32_t)__bfloat16_as_ushort(__float2bfloat16(src[8]));
        Wkp[kp * 32 + gq] = l16 | (h16 << 16);
    }
    // xq[b][t][gq] = embproj[token][gq] + bg[gq] + theta[gq]
    #pragma unroll
    for (int it = 0; it < 16; it++) {
        int p  = tid + it * 512;
        int bb = p >> 12, r = p & 4095;
        int t  = r >> 5, gq = r & 31;
        int token = sentence[t * B_ + b0 + bb];
        (bb ? xq1 : xq0)[t * 32 + gq] =
            g_embproj[token * GQ + gq] + bg[gq] + theta[gq];
    }
    // per-thread Wp slices for j = tid and j = tid + 512
    float wpreg[64], bpv[8];
    #pragma unroll
    for (int k = 0; k < 32; k++) {
        wpreg[k]      = Wp[k * H_ + tid];
        wpreg[32 + k] = Wp[k * H_ + tid + 512];
    }
    #pragma unroll
    for (int g = 0; g < 4; g++) {
        bpv[g]     = bp[g * H_ + tid];
        bpv[4 + g] = bp[g * H_ + tid + 512];
    }

    h0s[tid] = 0.f; h0s[tid + 512] = 0.f;
    h1s[tid] = 0.f; h1s[tid + 512] = 0.f;
    float h0a = 0.f, h0b = 0.f, h1a = 0.f, h1b = 0.f;
    float c0a = 0.f, c0b = 0.f, c1a = 0.f, c1b = 0.f;
    __syncthreads();

    // warp's k-pair slice: kp in [32*warp, 32*warp+32)  (k in [64w, 64w+64))
    const uint32_t* wrow = Wkp + (32 * warp) * 32 + lane;
    const float4*   h0v  = (const float4*)(h0s + 64 * warp);   // 16 float4
    const float4*   h1v  = (const float4*)(h1s + 64 * warp);
    const int rgq = 2 * warp + (lane >> 4);   // gq reduced by this half-warp
    const int ri  = lane & 15;

    for (int t = 0; t < T_; t++) {
        // matvec partials: lane = gq, this warp's 64 k values
        float a0 = 0.f, a1 = 0.f;
        #pragma unroll
        for (int i = 0; i < 16; i++) {
            uint32_t w0 = wrow[(2 * i) * 32];        // kp = 32w + 2i
            uint32_t w1 = wrow[(2 * i + 1) * 32];
            float4 hv0 = h0v[i];                      // h[64w+4i .. +3] (broadcast)
            float4 hv1 = h1v[i];
            a0 = fmaf(bflo(w0), hv0.x, a0); a0 = fmaf(bfhi(w0), hv0.y, a0);
            a0 = fmaf(bflo(w1), hv0.z, a0); a0 = fmaf(bfhi(w1), hv0.w, a0);
            a1 = fmaf(bflo(w0), hv1.x, a1); a1 = fmaf(bfhi(w0), hv1.y, a1);
            a1 = fmaf(bflo(w1), hv1.z, a1); a1 = fmaf(bfhi(w1), hv1.w, a1);
        }
        red0[warp * 33 + lane] = a0;
        red1[warp * 33 + lane] = a1;
        __syncthreads();
        {
            // half-warp reduces 16 warp-partials for gq = rgq
            float v0 = red0[ri * 33 + rgq];
            float v1 = red1[ri * 33 + rgq];
            #pragma unroll
            for (int off = 8; off > 0; off >>= 1) {
                v0 += __shfl_xor_sync(~0u, v0, off);
                v1 += __shfl_xor_sync(~0u, v1, off);
            }
            if (ri == 0) {
                qc0[rgq] = __cosf(v0 + xq0[t * 32 + rgq]);
                qc1[rgq] = __cosf(v1 + xq1[t * 32 + rgq]);
            }
        }
        __syncthreads();

        const float4* q0 = (const float4*)qc0;
        const float4* q1 = (const float4*)qc1;
        gate_update(q0, wpreg,      bpv,     c0a, h0a);
        gate_update(q0, wpreg + 32, bpv + 4, c0b, h0b);
        gate_update(q1, wpreg,      bpv,     c1a, h1a);
        gate_update(q1, wpreg + 32, bpv + 4, c1b, h1b);

        size_t base = ((size_t)t * B_ + b0) * H_;
        g_lstm[base + tid]            = __float2bfloat16(h0a);
        g_lstm[base + tid + 512]      = __float2bfloat16(h0b);
        g_lstm[base + H_ + tid]       = __float2bfloat16(h1a);
        g_lstm[base + H_ + tid + 512] = __float2bfloat16(h1b);
        h0s[tid] = h0a; h0s[tid + 512] = h0b;
        h1s[tid] = h1a; h1s[tid + 512] = h1b;
        __syncthreads();
    }
}

// ---------------- K3: fused tag GEMM (bf16 WMMA, 3-stage, 1 sync/iter) ------
// block = one (t, 128-tag chunk): tile 256(b) x 128(tags), K = 1024, KT = 64.
// b_tag cancels in batch-axis log_softmax.
#define A_STG (256 * 72)     // halves per A stage (ld = 72)
#define B_STG (64 * 136)     // halves per B stage (ld = 136)
#define TAG_SMEM (3 * (A_STG + B_STG) * 2)   // 162816 B; epilogue aliases

__global__ __launch_bounds__(256, 1) void tag_kernel(float* __restrict__ out) {
    extern __shared__ char smraw[];
    __nv_bfloat16* Asm = (__nv_bfloat16*)smraw;        // 3 stages 256x72
    __nv_bfloat16* Bsm = Asm + 3 * A_STG;              // 3 stages 64x136
    float* Osm = (float*)smraw;                        // 256 x 136 fp32 (alias)
    float* red = Osm + 256 * 136;

    const int tid = threadIdx.x;
    const int t   = blockIdx.y;
    const int c0  = blockIdx.x * 128;
    const int w   = tid >> 5;
    const int wy  = w >> 1;        // 0..3 -> 64-row block
    const int wx  = w & 1;         // 0..1 -> 64-col block

    wmma::fragment<wmma::accumulator, 16, 16, 16, float> acc[4][4];
    #pragma unroll
    for (int i = 0; i < 4; i++)
        #pragma unroll
        for (int j = 0; j < 4; j++) wmma::fill_fragment(acc[i][j], 0.f);

    auto issue_tile = [&](int kt) {
        int s  = kt % 3;
        int k0 = kt * 64;
        __nv_bfloat16* As = Asm + s * A_STG;
        __nv_bfloat16* Bs = Bsm + s * B_STG;
        #pragma unroll
        for (int i = 0; i < 8; i++) {             // A: 256x64 = 2048 cp16
            int e = tid + i * 256;
            int row = e >> 3, c8 = (e & 7) * 8;
            cp16(&As[row * 72 + c8],
                 &g_lstm[((size_t)t * B_ + row) * H_ + k0 + c8]);
        }
        #pragma unroll
        for (int i = 0; i < 4; i++) {             // B: 64x128 = 1024 cp16
            int e = tid + i * 256;
            int row = e >> 4, c8 = (e & 15) * 8;
            cp16(&Bs[row * 136 + c8],
                 &g_wtag[(size_t)(k0 + row) * TAGS_ + c0 + c8]);
        }
        asm volatile("cp.async.commit_group;\n" ::);
    };

    issue_tile(0);
    issue_tile(1);
    for (int kt = 0; kt < 16; kt++) {
        if (kt < 15) asm volatile("cp.async.wait_group 1;\n" ::);
        else         asm volatile("cp.async.wait_group 0;\n" ::);
        __syncthreads();   // stage kt ready for ALL warps; also proves compute
                           // kt-1 finished everywhere (safe to overwrite kt+2%3)
        int s = kt % 3;
        const __nv_bfloat16* As = Asm + s * A_STG;
        const __nv_bfloat16* Bs = Bsm + s * B_STG;
        #pragma unroll
        for (int ks = 0; ks < 64; ks += 16) {
            wmma::fragment<wmma::matrix_a, 16, 16, 16, __nv_bfloat16, wmma::row_major> af[4];
            wmma::fragment<wmma::matrix_b, 16, 16, 16, __nv_bfloat16, wmma::row_major> bf[4];
            #pragma unroll
            for (int i = 0; i < 4; i++)
                wmma::load_matrix_sync(af[i], &As[(wy * 64 + i * 16) * 72 + ks], 72);
            #pragma unroll
            for (int j = 0; j < 4; j++)
                wmma::load_matrix_sync(bf[j], &Bs[ks * 136 + wx * 64 + j * 16], 136);
            #pragma unroll
            for (int i = 0; i < 4; i++)
                #pragma unroll
                for (int j = 0; j < 4; j++)
                    wmma::mma_sync(acc[i][j], af[i], bf[j], acc[i][j]);
        }
        if (kt + 2 < 16) issue_tile(kt + 2);
    }
    __syncthreads();   // all compute done before Osm aliases stage buffers

    #pragma unroll
    for (int i = 0; i < 4; i++)
        #pragma unroll
        for (int j = 0; j < 4; j++)
            wmma::store_matrix_sync(&Osm[(wy * 64 + i * 16) * 136 + wx * 64 + j * 16],
                                    acc[i][j], 136, wmma::mem_row_major);
    __syncthreads();

    // log_softmax over the 256 rows (batch) per column (tag); 256 threads
    const int p = tid >> 7;        // 0..1, 128 rows each
    const int c = tid & 127;
    float m = -1e30f;
    #pragma unroll 8
    for (int i = 0; i < 128; i++) m = fmaxf(m, Osm[(p * 128 + i) * 136 + c]);
    red[p * 128 + c] = m;
    __syncthreads();
    float M = fmaxf(red[c], red[128 + c]);
    float ssum = 0.f;
    #pragma unroll 8
    for (int i = 0; i < 128; i++) ssum += __expf(Osm[(p * 128 + i) * 136 + c] - M);
    __syncthreads();
    red[p * 128 + c] = ssum;
    __syncthreads();
    float lse = M + logf(red[c] + red[128 + c]);
    #pragma unroll 8
    for (int i = 0; i < 128; i++) {
        int b = p * 128 + i;
        out[((size_t)t * B_ + b) * TAGS_ + c0 + c] = Osm[b * 136 + c] - lse;
    }
}

// ---------------- launch -----------------------------------------------------
extern "C" void kernel_launch(void* const* d_in, const int* in_sizes, int n_in,
                              void* d_out, int out_size) {
    const int*   sentence = (const int*)  d_in[0];
    const float* emb      = (const float*)d_in[1];
    const float* Wg       = (const float*)d_in[2];
    const float* bg       = (const float*)d_in[3];
    const float* theta    = (const float*)d_in[4];
    const float* Wp       = (const float*)d_in[5];
    const float* bp       = (const float*)d_in[6];
    const float* W_tag    = (const float*)d_in[7];
    // d_in[8] = b_tag: cancels in log_softmax over batch axis -> unused
    float* out = (float*)d_out;

    cudaFuncSetAttribute(lstm_kernel, cudaFuncAttributeMaxDynamicSharedMemorySize, LSTM_SMEM);
    cudaFuncSetAttribute(tag_kernel,  cudaFuncAttributeMaxDynamicSharedMemorySize, TAG_SMEM);

    wtag_convert<<<(H_ * TAGS_) / 256, 256>>>(W_tag);
    embproj_kernel<<<V_ / 128, 256>>>(emb, Wg);
    lstm_kernel<<<B_ / 2, 512, LSTM_SMEM>>>(sentence, Wg, bg, theta, Wp, bp);
    dim3 g3(TAGS_ / 128, T_);
    tag_kernel<<<g3, 256, TAG_SMEM>>>(out);
}